// round 16
// baseline (speedup 1.0000x reference)
#include <cuda_runtime.h>
#include <cstdint>

#define J     17
#define E     4096
#define M16   16
#define K1    (2*E)
#define K2    E
#define TKA   256          // GEMM1 K-slab -> 32 slabs
#define TKB   128          // GEMM2 K-slab -> 32 slabs
#define NSLAB 32
#define NBLK  256          // fused grid size (2 CTAs/SM co-resident)
#define LN_EPS 1e-5f
#define STG_BYTES 16384    // one W stage: 8 rows x 512 cols x 4B
#define NSTAGES 3

typedef unsigned long long ull;

// -------- device scratch --------
__device__ float    d_h[M16 * E];                // 256 KB hidden
__device__ float    d_partial[NSLAB * M16 * E];  // 8 MB
__device__ float2   d_stats[M16 * 16];           // per-(row,chunk) sum/sumsq
__device__ unsigned d_ctr[8];                    // monotone sync counters

__device__ __forceinline__ void fma2(ull& d, ull a, ull b) {
    asm("fma.rn.f32x2 %0, %1, %2, %0;" : "+l"(d) : "l"(a), "l"(b));
}
__device__ __forceinline__ ull dup_pack(float p) {
    unsigned u = __float_as_uint(p);
    return ((ull)u << 32) | (ull)u;
}
__device__ __forceinline__ float lo_f(ull v) {
    return __uint_as_float((unsigned)v);
}
__device__ __forceinline__ float hi_f(ull v) {
    return __uint_as_float((unsigned)(v >> 32));
}

// ---- ticket grid-sync: no reset needed, replay-safe (monotone counter) ----
__device__ __forceinline__ void gsync(unsigned* ctr) {
    __syncthreads();
    if (threadIdx.x == 0) {
        __threadfence();
        unsigned t = atomicAdd(ctr, 1u);
        unsigned target = (t / NBLK + 1u) * NBLK;
        while (atomicAdd(ctr, 0u) < target) { }
        __threadfence();
    }
    __syncthreads();
}

// ============================================================
// GEMM phase. 2 cols/thread, per-thread barrier-free cp.async
// 3-stage W ring (8B per row per thread). Act slab as PLAIN floats:
// ulonglong2 broadcast load yields bone-pair packed f32x2 operands.
// acc[c][b] = {bone 2b, bone 2b+1} at col n+c. acc = 32 regs.
// bx=bid&7 (512-col block), by=bid>>3 (slab 0..31).
// MODE 0: pair gather; MODE 1: h gather.
// ============================================================
template<int TK, int MODE>
__device__ __forceinline__ void gemm_phase(
    char* smem, int bid, int tid,
    const float* __restrict__ W,
    const float* __restrict__ act,
    const int*   __restrict__ bp,
    float* __restrict__ partial)
{
    float* spf = reinterpret_cast<float*>(smem);       // TK*16 plain floats
    char*  wst = smem + (size_t)TK * M16 * 4;          // 3 x 16KB W stages

    int bx = bid & 7;
    int by = bid >> 3;
    int k0 = by * TK;

    // activation slab fill (gather, plain float)
    {
        int m = tid & 15;
        const float *r0, *r1;
        if (MODE == 0) {
            r0 = act + (size_t)bp[2 * m] * E;
            r1 = act + (size_t)bp[2 * m + 1] * E;
        } else {
            r0 = act + (size_t)m * E;
            r1 = r0;
        }
        #pragma unroll
        for (int i = 0; i < (TK * M16) / 256; i++) {
            int kl = (tid >> 4) + i * 16;
            int k = k0 + kl;
            float p;
            if (MODE == 0) {
                int col = k & (E - 1);
                p = (k < E) ? r0[col] : r1[col];
            } else {
                p = r0[k];
            }
            spf[kl * M16 + m] = p;
        }
    }

    int n = bx * 512 + tid * 2;
    const float* wp = W + (size_t)k0 * E + n;
    unsigned wsaddr = (unsigned)__cvta_generic_to_shared(wst) + tid * 8;
    const int NSTG = TK / 8;

    #pragma unroll
    for (int s = 0; s < NSTAGES; s++) {
        if (s < NSTG) {
            #pragma unroll
            for (int r = 0; r < 8; r++) {
                asm volatile("cp.async.ca.shared.global [%0], [%1], 8;\n" ::
                    "r"(wsaddr + s * STG_BYTES + r * 2048),
                    "l"(wp + (size_t)(s * 8 + r) * E) : "memory");
            }
        }
        asm volatile("cp.async.commit_group;\n" ::: "memory");
    }

    __syncthreads();   // slab ready

    ull acc[2][8];     // [col][bone-pair]
    #pragma unroll
    for (int c = 0; c < 2; c++)
        #pragma unroll
        for (int b = 0; b < 8; b++) acc[c][b] = 0ULL;

    unsigned bufoff = 0;
    #pragma unroll 1
    for (int s = 0; s < NSTG; s++) {
        asm volatile("cp.async.wait_group 2;\n" ::: "memory");

        #pragma unroll
        for (int r = 0; r < 8; r++) {
            float2 w2 = *reinterpret_cast<const float2*>(
                wst + bufoff + r * 2048 + tid * 8);
            ull wd0 = dup_pack(w2.x);
            ull wd1 = dup_pack(w2.y);
            const ulonglong2* row = reinterpret_cast<const ulonglong2*>(
                spf + (s * 8 + r) * M16);
            #pragma unroll
            for (int q = 0; q < 4; q++) {
                ulonglong2 a = row[q];       // bone pairs 2q, 2q+1
                fma2(acc[0][2*q  ], wd0, a.x);
                fma2(acc[1][2*q  ], wd1, a.x);
                fma2(acc[0][2*q+1], wd0, a.y);
                fma2(acc[1][2*q+1], wd1, a.y);
            }
        }

        if (s + NSTAGES < NSTG) {
            #pragma unroll
            for (int r = 0; r < 8; r++) {
                asm volatile("cp.async.ca.shared.global [%0], [%1], 8;\n" ::
                    "r"(wsaddr + bufoff + r * 2048),
                    "l"(wp + (size_t)((s + NSTAGES) * 8 + r) * E) : "memory");
            }
        }
        asm volatile("cp.async.commit_group;\n" ::: "memory");

        bufoff += STG_BYTES;
        if (bufoff == NSTAGES * STG_BYTES) bufoff = 0;
    }

    // epilogue: acc[c][b] lo->row 2b, hi->row 2b+1, cols n..n+1
    size_t base = ((size_t)by * M16) * E + n;
    #pragma unroll
    for (int b = 0; b < 8; b++) {
        float2 vlo, vhi;
        vlo.x = lo_f(acc[0][b]); vlo.y = lo_f(acc[1][b]);
        vhi.x = hi_f(acc[0][b]); vhi.y = hi_f(acc[1][b]);
        *reinterpret_cast<float2*>(&partial[base + (size_t)(2*b)   * E]) = vlo;
        *reinterpret_cast<float2*>(&partial[base + (size_t)(2*b+1) * E]) = vhi;
    }
}

// ============================================================
// Reduce phase: 256 blocks = 16 rows x 16 chunks (64 float4 each).
// Thread quarters split the 32 slabs (8 each); v kept in regs across
// the internal gsync; then LN (+ReLU) apply. Cross-phase reads __ldcg.
// ============================================================
template<bool RELU>
__device__ __forceinline__ void reduce_phase(
    char* smem, int bid, int tid,
    const float4* __restrict__ bias4,
    const float4* __restrict__ gamma4,
    const float4* __restrict__ beta4,
    float4* __restrict__ out4,
    float2* __restrict__ stats,
    unsigned* ctr)
{
    int m  = bid >> 4;
    int ch = bid & 15;
    int c  = tid & 63;
    int q  = tid >> 6;
    int n4 = ch * 64 + c;

    const float4* p = reinterpret_cast<const float4*>(d_partial)
                    + (size_t)m * (E / 4) + n4;
    const size_t stride = (size_t)M16 * (E / 4);

    float4 a[4];
    a[0] = (q == 0) ? __ldcg(&bias4[n4]) : make_float4(0.f, 0.f, 0.f, 0.f);
    #pragma unroll
    for (int r = 1; r < 4; r++) a[r] = make_float4(0.f, 0.f, 0.f, 0.f);

    int s0 = q * 8;
    #pragma unroll
    for (int ks = 0; ks < 8; ks += 4) {
        #pragma unroll
        for (int r = 0; r < 4; r++) {
            float4 t = __ldcg(&p[(size_t)(s0 + ks + r) * stride]);
            a[r].x += t.x; a[r].y += t.y; a[r].z += t.z; a[r].w += t.w;
        }
    }
    a[0].x += a[1].x; a[0].y += a[1].y; a[0].z += a[1].z; a[0].w += a[1].w;
    a[2].x += a[3].x; a[2].y += a[3].y; a[2].z += a[3].z; a[2].w += a[3].w;
    float4 v;
    v.x = a[0].x + a[2].x; v.y = a[0].y + a[2].y;
    v.z = a[0].z + a[2].z; v.w = a[0].w + a[2].w;

    float4* qbuf = reinterpret_cast<float4*>(smem);            // [4][64]
    float*  wsum = reinterpret_cast<float*>(smem + 4096);      // [4]
    if (q != 0) qbuf[q * 64 + c] = v;
    __syncthreads();
    if (q == 0) {
        float4 b1 = qbuf[64 + c], b2 = qbuf[128 + c], b3 = qbuf[192 + c];
        v.x += b1.x + b2.x + b3.x; v.y += b1.y + b2.y + b3.y;
        v.z += b1.z + b2.z + b3.z; v.w += b1.w + b2.w + b3.w;
        float s  = (v.x + v.y) + (v.z + v.w);
        float sq = (v.x * v.x + v.y * v.y) + (v.z * v.z + v.w * v.w);
        #pragma unroll
        for (int off = 16; off > 0; off >>= 1) {
            s  += __shfl_down_sync(0xffffffffu, s,  off);
            sq += __shfl_down_sync(0xffffffffu, sq, off);
        }
        if ((tid & 31) == 0) {
            wsum[(tid >> 5) * 2]     = s;
            wsum[(tid >> 5) * 2 + 1] = sq;
        }
    }
    __syncthreads();
    if (tid == 0)
        stats[m * 16 + ch] = make_float2(wsum[0] + wsum[2], wsum[1] + wsum[3]);

    gsync(ctr);   // all chunk stats visible

    if (q == 0) {
        float sum = 0.f, sq = 0.f;
        #pragma unroll
        for (int cc = 0; cc < 16; cc++) {
            float2 s = __ldcg(&stats[m * 16 + cc]);
            sum += s.x; sq += s.y;
        }
        float mu   = sum * (1.0f / E);
        float var  = sq * (1.0f / E) - mu * mu;
        float rstd = rsqrtf(var + LN_EPS);

        float4 g = __ldcg(&gamma4[n4]);
        float4 b = __ldcg(&beta4[n4]);
        float4 y;
        y.x = (v.x - mu) * rstd * g.x + b.x;
        y.y = (v.y - mu) * rstd * g.y + b.y;
        y.z = (v.z - mu) * rstd * g.z + b.z;
        y.w = (v.w - mu) * rstd * g.w + b.w;
        if (RELU) {
            y.x = fmaxf(y.x, 0.f); y.y = fmaxf(y.y, 0.f);
            y.z = fmaxf(y.z, 0.f); y.w = fmaxf(y.w, 0.f);
        }
        out4[(size_t)m * (E / 4) + n4] = y;
    }
}

// ============================================================
// ONE fused kernel: normalize -> GEMM1 -> reduce1/LN/ReLU -> GEMM2
// -> reduce2/LN. grid=256, block=256, 64 KB dynamic smem,
// 2 CTAs/SM forced => whole grid co-resident => gsync is safe.
// ============================================================
__global__ void __launch_bounds__(256, 2) fused_kernel(
    const float* __restrict__ emb,
    const float* __restrict__ W1, const float* __restrict__ b1,
    const float* __restrict__ g1, const float* __restrict__ be1,
    const float* __restrict__ W2, const float* __restrict__ b2,
    const float* __restrict__ g2, const float* __restrict__ be2,
    const int*   __restrict__ bp,
    float* __restrict__ out_joint, float* __restrict__ out_bone)
{
    extern __shared__ char smem[];
    int bid = blockIdx.x;
    int tid = threadIdx.x;

    // ---- phase 0: L2-normalize joints (blocks 0..16) ----
    if (bid < J) {
        float* red = reinterpret_cast<float*>(smem);
        const float4* xr4 = reinterpret_cast<const float4*>(emb + (size_t)bid * E);
        float4 v[4];
        float s = 0.f;
        #pragma unroll
        for (int i = 0; i < 4; i++) {
            v[i] = xr4[tid + i * 256];
            s += v[i].x * v[i].x + v[i].y * v[i].y
               + v[i].z * v[i].z + v[i].w * v[i].w;
        }
        red[tid] = s;
        __syncthreads();
        for (int off = 128; off > 0; off >>= 1) {
            if (tid < off) red[tid] += red[tid + off];
            __syncthreads();
        }
        float inv = 64.0f / fmaxf(sqrtf(red[0]), 1e-12f);
        float4* o4 = reinterpret_cast<float4*>(out_joint + (size_t)bid * E);
        #pragma unroll
        for (int i = 0; i < 4; i++) {
            float4 y;
            y.x = v[i].x * inv; y.y = v[i].y * inv;
            y.z = v[i].z * inv; y.w = v[i].w * inv;
            o4[tid + i * 256] = y;
        }
    }
    gsync(&d_ctr[0]);

    // ---- phase 1: GEMM1 (pair gather) ----
    gemm_phase<TKA, 0>(smem, bid, tid, W1, out_joint, bp, d_partial);
    gsync(&d_ctr[1]);

    // ---- phase 2: reduce1 + LN + ReLU -> d_h (internal gsync on ctr[2]) ----
    reduce_phase<true>(smem, bid, tid,
        (const float4*)b1, (const float4*)g1, (const float4*)be1,
        (float4*)d_h, d_stats, &d_ctr[2]);
    gsync(&d_ctr[3]);

    // ---- phase 3: GEMM2 (h gather) ----
    gemm_phase<TKB, 1>(smem, bid, tid, W2, d_h, nullptr, d_partial);
    gsync(&d_ctr[4]);

    // ---- phase 4: reduce2 + LN -> bone features (internal gsync ctr[5]) ----
    reduce_phase<false>(smem, bid, tid,
        (const float4*)b2, (const float4*)g2, (const float4*)be2,
        (float4*)out_bone, d_stats, &d_ctr[5]);
}

// ============================================================
// launcher — 1 launch
// ============================================================
extern "C" void kernel_launch(void* const* d_in, const int* in_sizes, int n_in,
                              void* d_out, int out_size)
{
    const float* emb = (const float*)d_in[0];
    const float* W1  = (const float*)d_in[1];
    const float* b1  = (const float*)d_in[2];
    const float* g1  = (const float*)d_in[3];
    const float* be1 = (const float*)d_in[4];
    const float* W2  = (const float*)d_in[5];
    const float* b2  = (const float*)d_in[6];
    const float* g2  = (const float*)d_in[7];
    const float* be2 = (const float*)d_in[8];
    const int*   bp  = (const int*)d_in[9];

    float* out = (float*)d_out;
    float* out_joint = out;                      // [17][4096]
    float* out_bone  = out + (size_t)J * E;      // [16][4096]

    const int smemsz = TKA * M16 * 4 + NSTAGES * STG_BYTES;  // 16KB + 48KB = 64 KB
    cudaFuncSetAttribute(fused_kernel,
        cudaFuncAttributeMaxDynamicSharedMemorySize, smemsz);

    fused_kernel<<<NBLK, 256, smemsz>>>(
        emb, W1, b1, g1, be1, W2, b2, g2, be2, bp, out_joint, out_bone);
}

// round 17
// speedup vs baseline: 1.1133x; 1.1133x over previous
#include <cuda_runtime.h>
#include <cuda_fp16.h>
#include <cstdint>

#define J     17
#define E     4096
#define M16   16
#define K1    (2*E)
#define K2    E
#define TKA   128          // GEMM1 K-slab -> 64 slabs
#define TKB   64           // GEMM2 K-slab -> 64 slabs
#define NBLK  256          // fused grid size (2 CTAs/SM co-resident)
#define LN_EPS 1e-5f
#define STG_BYTES 32768    // one W stage: 8 rows x 1024 cols x 4B
#define NSTAGES 3

typedef unsigned long long ull;

// -------- device scratch --------
__device__ float    d_h[M16 * E];                 // 256 KB hidden
__device__ ull      d_partial[64 * M16 * E / 4];  // 8 MB fp16 partials (4/ull)
__device__ float2   d_stats[M16 * 16];            // per-(row,chunk) sum/sumsq
__device__ unsigned d_ctr[8];                     // monotone sync counters

__device__ __forceinline__ void fma2(ull& d, ull a, ull b) {
    asm("fma.rn.f32x2 %0, %1, %2, %0;" : "+l"(d) : "l"(a), "l"(b));
}
__device__ __forceinline__ ull dup_pack(float p) {
    unsigned u = __float_as_uint(p);
    return ((ull)u << 32) | (ull)u;
}
__device__ __forceinline__ float lo_f(ull v) {
    return __uint_as_float((unsigned)v);
}
__device__ __forceinline__ float hi_f(ull v) {
    return __uint_as_float((unsigned)(v >> 32));
}
// pack 4 floats -> 4 fp16 in one ull (cols ascending)
__device__ __forceinline__ ull pack4h(float a, float b, float c, float d) {
    __half2 h01 = __floats2half2_rn(a, b);
    __half2 h23 = __floats2half2_rn(c, d);
    unsigned u01 = *reinterpret_cast<unsigned*>(&h01);
    unsigned u23 = *reinterpret_cast<unsigned*>(&h23);
    return ((ull)u23 << 32) | (ull)u01;
}
__device__ __forceinline__ float4 unpack4h(ull v) {
    unsigned u01 = (unsigned)v;
    unsigned u23 = (unsigned)(v >> 32);
    __half2 h01 = *reinterpret_cast<__half2*>(&u01);
    __half2 h23 = *reinterpret_cast<__half2*>(&u23);
    float2 f01 = __half22float2(h01);
    float2 f23 = __half22float2(h23);
    return make_float4(f01.x, f01.y, f23.x, f23.y);
}

// ---- ticket grid-sync: no reset needed, replay-safe (monotone counter) ----
__device__ __forceinline__ void gsync(unsigned* ctr) {
    __syncthreads();
    if (threadIdx.x == 0) {
        __threadfence();
        unsigned t = atomicAdd(ctr, 1u);
        unsigned target = (t / NBLK + 1u) * NBLK;
        while (atomicAdd(ctr, 0u) < target) { }
        __threadfence();
    }
    __syncthreads();
}

// ============================================================
// GEMM phase (round-15 body). 4 cols/thread, per-thread barrier-free
// cp.async 3-stage W ring. Act slab PLAIN floats: ulonglong2 broadcast
// yields bone-pair packed f32x2 operands. acc[c][b]={bone2b,bone2b+1}.
// Epilogue packs fp32 accs -> fp16 partials (8B per bone-row).
// bx=bid&3 (1024-col block), by=bid>>2 (slab).
// MODE 0: pair gather; MODE 1: h gather.
// ============================================================
template<int TK, int MODE>
__device__ __forceinline__ void gemm_phase(
    char* smem, int bid, int tid,
    const float* __restrict__ W,
    const float* __restrict__ act,
    const int*   __restrict__ bp,
    ull* __restrict__ partial)
{
    float* spf = reinterpret_cast<float*>(smem);       // TK*16 plain floats
    char*  wst = smem + (size_t)TK * M16 * 4;          // 3 x 32KB W stages

    int bx = bid & 3;
    int by = bid >> 2;
    int k0 = by * TK;

    // activation slab fill (gather, plain float)
    {
        int m = tid & 15;
        const float *r0, *r1;
        if (MODE == 0) {
            r0 = act + (size_t)bp[2 * m] * E;
            r1 = act + (size_t)bp[2 * m + 1] * E;
        } else {
            r0 = act + (size_t)m * E;
            r1 = r0;
        }
        #pragma unroll
        for (int i = 0; i < (TK * M16) / 256; i++) {
            int kl = (tid >> 4) + i * 16;
            int k = k0 + kl;
            float p;
            if (MODE == 0) {
                int col = k & (E - 1);
                p = (k < E) ? r0[col] : r1[col];
            } else {
                p = r0[k];
            }
            spf[kl * M16 + m] = p;
        }
    }

    int n = bx * 1024 + tid * 4;
    const float* wp = W + (size_t)k0 * E + n;
    unsigned wsaddr = (unsigned)__cvta_generic_to_shared(wst) + tid * 16;
    const int NSTG = TK / 8;

    #pragma unroll
    for (int s = 0; s < NSTAGES; s++) {
        if (s < NSTG) {
            #pragma unroll
            for (int r = 0; r < 8; r++) {
                asm volatile("cp.async.cg.shared.global [%0], [%1], 16;\n" ::
                    "r"(wsaddr + s * STG_BYTES + r * 4096),
                    "l"(wp + (size_t)(s * 8 + r) * E) : "memory");
            }
        }
        asm volatile("cp.async.commit_group;\n" ::: "memory");
    }

    __syncthreads();   // slab ready

    ull acc[4][8];     // [col][bone-pair]
    #pragma unroll
    for (int c = 0; c < 4; c++)
        #pragma unroll
        for (int b = 0; b < 8; b++) acc[c][b] = 0ULL;

    unsigned bufoff = 0;
    #pragma unroll 1
    for (int s = 0; s < NSTG; s++) {
        asm volatile("cp.async.wait_group 2;\n" ::: "memory");

        #pragma unroll
        for (int r = 0; r < 8; r++) {
            float4 w4 = *reinterpret_cast<const float4*>(
                wst + bufoff + r * 4096 + tid * 16);
            ull wd0 = dup_pack(w4.x);
            ull wd1 = dup_pack(w4.y);
            ull wd2 = dup_pack(w4.z);
            ull wd3 = dup_pack(w4.w);
            const ulonglong2* row = reinterpret_cast<const ulonglong2*>(
                spf + (s * 8 + r) * M16);
            #pragma unroll
            for (int q = 0; q < 4; q++) {
                ulonglong2 a = row[q];       // bone pairs 2q, 2q+1
                fma2(acc[0][2*q  ], wd0, a.x);
                fma2(acc[1][2*q  ], wd1, a.x);
                fma2(acc[2][2*q  ], wd2, a.x);
                fma2(acc[3][2*q  ], wd3, a.x);
                fma2(acc[0][2*q+1], wd0, a.y);
                fma2(acc[1][2*q+1], wd1, a.y);
                fma2(acc[2][2*q+1], wd2, a.y);
                fma2(acc[3][2*q+1], wd3, a.y);
            }
        }

        if (s + NSTAGES < NSTG) {
            #pragma unroll
            for (int r = 0; r < 8; r++) {
                asm volatile("cp.async.cg.shared.global [%0], [%1], 16;\n" ::
                    "r"(wsaddr + bufoff + r * 4096),
                    "l"(wp + (size_t)((s + NSTAGES) * 8 + r) * E) : "memory");
            }
        }
        asm volatile("cp.async.commit_group;\n" ::: "memory");

        bufoff += STG_BYTES;
        if (bufoff == NSTAGES * STG_BYTES) bufoff = 0;
    }

    // epilogue: fp16-pack. acc[c][b] lo->row 2b, hi->row 2b+1, cols n..n+3
    int col4 = bx * 256 + tid;                       // n/4
    size_t base = ((size_t)by * M16) * (E / 4) + col4;
    #pragma unroll
    for (int b = 0; b < 8; b++) {
        ull lop = pack4h(lo_f(acc[0][b]), lo_f(acc[1][b]),
                         lo_f(acc[2][b]), lo_f(acc[3][b]));
        ull hip = pack4h(hi_f(acc[0][b]), hi_f(acc[1][b]),
                         hi_f(acc[2][b]), hi_f(acc[3][b]));
        partial[base + (size_t)(2*b)   * (E / 4)] = lop;
        partial[base + (size_t)(2*b+1) * (E / 4)] = hip;
    }
}

// ============================================================
// Reduce phase: 256 blocks = 16 rows x 16 chunks (64 float4 each).
// Thread quarters split the 64 slabs (16 each, fp16 unpack, fp32 acc);
// v kept in regs across the internal gsync; then LN (+ReLU) apply.
// ============================================================
template<bool RELU>
__device__ __forceinline__ void reduce_phase(
    char* smem, int bid, int tid,
    const float4* __restrict__ bias4,
    const float4* __restrict__ gamma4,
    const float4* __restrict__ beta4,
    float4* __restrict__ out4,
    float2* __restrict__ stats,
    unsigned* ctr)
{
    int m  = bid >> 4;
    int ch = bid & 15;
    int c  = tid & 63;
    int q  = tid >> 6;
    int n4 = ch * 64 + c;

    const ull* p = d_partial + (size_t)m * (E / 4) + n4;
    const size_t stride = (size_t)M16 * (E / 4);

    float4 a[4];
    a[0] = (q == 0) ? __ldcg(&bias4[n4]) : make_float4(0.f, 0.f, 0.f, 0.f);
    #pragma unroll
    for (int r = 1; r < 4; r++) a[r] = make_float4(0.f, 0.f, 0.f, 0.f);

    int s0 = q * 16;
    #pragma unroll
    for (int ks = 0; ks < 16; ks += 4) {
        #pragma unroll
        for (int r = 0; r < 4; r++) {
            float4 t = unpack4h(__ldcg(&p[(size_t)(s0 + ks + r) * stride]));
            a[r].x += t.x; a[r].y += t.y; a[r].z += t.z; a[r].w += t.w;
        }
    }
    a[0].x += a[1].x; a[0].y += a[1].y; a[0].z += a[1].z; a[0].w += a[1].w;
    a[2].x += a[3].x; a[2].y += a[3].y; a[2].z += a[3].z; a[2].w += a[3].w;
    float4 v;
    v.x = a[0].x + a[2].x; v.y = a[0].y + a[2].y;
    v.z = a[0].z + a[2].z; v.w = a[0].w + a[2].w;

    float4* qbuf = reinterpret_cast<float4*>(smem);            // [4][64]
    float*  wsum = reinterpret_cast<float*>(smem + 4096);      // [4]
    if (q != 0) qbuf[q * 64 + c] = v;
    __syncthreads();
    if (q == 0) {
        float4 b1 = qbuf[64 + c], b2 = qbuf[128 + c], b3 = qbuf[192 + c];
        v.x += b1.x + b2.x + b3.x; v.y += b1.y + b2.y + b3.y;
        v.z += b1.z + b2.z + b3.z; v.w += b1.w + b2.w + b3.w;
        float s  = (v.x + v.y) + (v.z + v.w);
        float sq = (v.x * v.x + v.y * v.y) + (v.z * v.z + v.w * v.w);
        #pragma unroll
        for (int off = 16; off > 0; off >>= 1) {
            s  += __shfl_down_sync(0xffffffffu, s,  off);
            sq += __shfl_down_sync(0xffffffffu, sq, off);
        }
        if ((tid & 31) == 0) {
            wsum[(tid >> 5) * 2]     = s;
            wsum[(tid >> 5) * 2 + 1] = sq;
        }
    }
    __syncthreads();
    if (tid == 0)
        stats[m * 16 + ch] = make_float2(wsum[0] + wsum[2], wsum[1] + wsum[3]);

    gsync(ctr);   // all chunk stats visible

    if (q == 0) {
        float sum = 0.f, sq = 0.f;
        #pragma unroll
        for (int cc = 0; cc < 16; cc++) {
            float2 s = __ldcg(&stats[m * 16 + cc]);
            sum += s.x; sq += s.y;
        }
        float mu   = sum * (1.0f / E);
        float var  = sq * (1.0f / E) - mu * mu;
        float rstd = rsqrtf(var + LN_EPS);

        float4 g = __ldcg(&gamma4[n4]);
        float4 b = __ldcg(&beta4[n4]);
        float4 y;
        y.x = (v.x - mu) * rstd * g.x + b.x;
        y.y = (v.y - mu) * rstd * g.y + b.y;
        y.z = (v.z - mu) * rstd * g.z + b.z;
        y.w = (v.w - mu) * rstd * g.w + b.w;
        if (RELU) {
            y.x = fmaxf(y.x, 0.f); y.y = fmaxf(y.y, 0.f);
            y.z = fmaxf(y.z, 0.f); y.w = fmaxf(y.w, 0.f);
        }
        out4[(size_t)m * (E / 4) + n4] = y;
    }
}

// ============================================================
// ONE fused kernel: normalize -> GEMM1 -> reduce1/LN/ReLU -> GEMM2
// -> reduce2/LN. grid=256, block=256, 104 KB dynamic smem,
// 2 CTAs/SM forced => whole grid co-resident => gsync is safe.
// ============================================================
__global__ void __launch_bounds__(256, 2) fused_kernel(
    const float* __restrict__ emb,
    const float* __restrict__ W1, const float* __restrict__ b1,
    const float* __restrict__ g1, const float* __restrict__ be1,
    const float* __restrict__ W2, const float* __restrict__ b2,
    const float* __restrict__ g2, const float* __restrict__ be2,
    const int*   __restrict__ bp,
    float* __restrict__ out_joint, float* __restrict__ out_bone)
{
    extern __shared__ char smem[];
    int bid = blockIdx.x;
    int tid = threadIdx.x;

    // ---- phase 0: L2-normalize joints (blocks 0..16) ----
    if (bid < J) {
        float* red = reinterpret_cast<float*>(smem);
        const float4* xr4 = reinterpret_cast<const float4*>(emb + (size_t)bid * E);
        float4 v[4];
        float s = 0.f;
        #pragma unroll
        for (int i = 0; i < 4; i++) {
            v[i] = xr4[tid + i * 256];
            s += v[i].x * v[i].x + v[i].y * v[i].y
               + v[i].z * v[i].z + v[i].w * v[i].w;
        }
        red[tid] = s;
        __syncthreads();
        for (int off = 128; off > 0; off >>= 1) {
            if (tid < off) red[tid] += red[tid + off];
            __syncthreads();
        }
        float inv = 64.0f / fmaxf(sqrtf(red[0]), 1e-12f);
        float4* o4 = reinterpret_cast<float4*>(out_joint + (size_t)bid * E);
        #pragma unroll
        for (int i = 0; i < 4; i++) {
            float4 y;
            y.x = v[i].x * inv; y.y = v[i].y * inv;
            y.z = v[i].z * inv; y.w = v[i].w * inv;
            o4[tid + i * 256] = y;
        }
    }
    gsync(&d_ctr[0]);

    // ---- phase 1: GEMM1 (pair gather) ----
    gemm_phase<TKA, 0>(smem, bid, tid, W1, out_joint, bp, d_partial);
    gsync(&d_ctr[1]);

    // ---- phase 2: reduce1 + LN + ReLU -> d_h (internal gsync on ctr[2]) ----
    reduce_phase<true>(smem, bid, tid,
        (const float4*)b1, (const float4*)g1, (const float4*)be1,
        (float4*)d_h, d_stats, &d_ctr[2]);
    gsync(&d_ctr[3]);

    // ---- phase 3: GEMM2 (h gather) ----
    gemm_phase<TKB, 1>(smem, bid, tid, W2, d_h, nullptr, d_partial);
    gsync(&d_ctr[4]);

    // ---- phase 4: reduce2 + LN -> bone features (internal gsync ctr[5]) ----
    reduce_phase<false>(smem, bid, tid,
        (const float4*)b2, (const float4*)g2, (const float4*)be2,
        (float4*)out_bone, d_stats, &d_ctr[5]);
}

// ============================================================
// launcher — 1 launch
// ============================================================
extern "C" void kernel_launch(void* const* d_in, const int* in_sizes, int n_in,
                              void* d_out, int out_size)
{
    const float* emb = (const float*)d_in[0];
    const float* W1  = (const float*)d_in[1];
    const float* b1  = (const float*)d_in[2];
    const float* g1  = (const float*)d_in[3];
    const float* be1 = (const float*)d_in[4];
    const float* W2  = (const float*)d_in[5];
    const float* b2  = (const float*)d_in[6];
    const float* g2  = (const float*)d_in[7];
    const float* be2 = (const float*)d_in[8];
    const int*   bp  = (const int*)d_in[9];

    float* out = (float*)d_out;
    float* out_joint = out;                      // [17][4096]
    float* out_bone  = out + (size_t)J * E;      // [16][4096]

    const int smemsz = TKA * M16 * 4 + NSTAGES * STG_BYTES;  // 8KB + 96KB = 104 KB
    cudaFuncSetAttribute(fused_kernel,
        cudaFuncAttributeMaxDynamicSharedMemorySize, smemsz);

    fused_kernel<<<NBLK, 256, smemsz>>>(
        emb, W1, b1, g1, be1, W2, b2, g2, be2, bp, out_joint, out_bone);
}